// round 1
// baseline (speedup 1.0000x reference)
#include <cuda_runtime.h>
#include <math.h>

#define D 128
static constexpr int MAXN = 51200;

// Scratch (no allocs allowed -> device globals)
__device__ float d_xa[MAXN * D];
__device__ float d_xp[MAXN * D];
__device__ float d_mj[MAXN * D];
__device__ float d_v [MAXN * D];
__device__ float d_t1[MAXN * D];

__device__ __forceinline__ float ssp(float x) {
    // shifted softplus: logaddexp(x,0) - log(2), numerically stable both tails
    return fmaxf(x, 0.0f) + log1pf(__expf(-fabsf(x))) - 0.69314718055994530942f;
}

// ---------------------------------------------------------------------------
// Prolog: xa = ssp(x); xp = u * xa
// ---------------------------------------------------------------------------
__global__ void prolog_kernel(const float* __restrict__ x,
                              const float* __restrict__ u,
                              float* __restrict__ xa,
                              float* __restrict__ xp,
                              int total) {
    int i = blockIdx.x * blockDim.x + threadIdx.x;
    if (i < total) {
        float a = ssp(x[i]);
        xa[i] = a;
        xp[i] = u[i & (D - 1)] * a;
    }
}

// ---------------------------------------------------------------------------
// GEMM: out = post( preact(A) @ W + bias [+ base] )
// A: [N,128], W: [128,128] row-major (k, n), bias: [128]
// Tile: BM=128, BN=128, BK=8; 256 threads; 8x8 microtile per thread.
// ---------------------------------------------------------------------------
template<bool PRE, bool POST, bool HASBASE>
__global__ __launch_bounds__(256, 2)
void mm128_kernel(const float* __restrict__ A,
                  const float* __restrict__ W,
                  const float* __restrict__ bias,
                  const float* __restrict__ base,
                  float* __restrict__ out,
                  int N) {
    __shared__ float As[8][132];   // padded to kill 2-way store conflict
    __shared__ float Bs[8][128];

    const int t    = threadIdx.x;
    const int row0 = blockIdx.x * 128;

    const int arow = t >> 1;            // 0..127
    const int acol = (t & 1) << 2;      // 0 or 4 (k offset within BK)
    const int wrow = t >> 5;            // 0..7
    const int wcol = (t & 31) << 2;     // 0..124

    const int mrow = (t >> 4) << 3;     // 0..120
    const int ncol = (t & 15) << 3;     // 0..120

    float acc[8][8];
    #pragma unroll
    for (int i = 0; i < 8; i++)
        #pragma unroll
        for (int j = 0; j < 8; j++)
            acc[i][j] = 0.0f;

    const int agr = row0 + arow;
    const bool avalid = (agr < N);

    for (int kc = 0; kc < 128; kc += 8) {
        float4 av;
        if (avalid) av = *reinterpret_cast<const float4*>(A + (size_t)agr * D + kc + acol);
        else        av = make_float4(0.f, 0.f, 0.f, 0.f);
        if (PRE) { av.x = ssp(av.x); av.y = ssp(av.y); av.z = ssp(av.z); av.w = ssp(av.w); }
        As[acol + 0][arow] = av.x;
        As[acol + 1][arow] = av.y;
        As[acol + 2][arow] = av.z;
        As[acol + 3][arow] = av.w;

        float4 wv = *reinterpret_cast<const float4*>(W + (size_t)(kc + wrow) * D + wcol);
        *reinterpret_cast<float4*>(&Bs[wrow][wcol]) = wv;

        __syncthreads();

        #pragma unroll
        for (int kk = 0; kk < 8; kk++) {
            float a[8], b[8];
            #pragma unroll
            for (int i = 0; i < 8; i++) a[i] = As[kk][mrow + i];
            #pragma unroll
            for (int j = 0; j < 8; j++) b[j] = Bs[kk][ncol + j];
            #pragma unroll
            for (int i = 0; i < 8; i++)
                #pragma unroll
                for (int j = 0; j < 8; j++)
                    acc[i][j] += a[i] * b[j];
        }
        __syncthreads();
    }

    float bv[8];
    #pragma unroll
    for (int j = 0; j < 8; j++) bv[j] = bias[ncol + j];

    #pragma unroll
    for (int i = 0; i < 8; i++) {
        int r = row0 + mrow + i;
        if (r < N) {
            size_t off = (size_t)r * D + ncol;
            #pragma unroll
            for (int j = 0; j < 8; j++) {
                float val = acc[i][j] + bv[j];
                if (HASBASE) val += base[off + j];
                if (POST) val = ssp(val);
                out[off + j] = val;
            }
        }
    }
}

// ---------------------------------------------------------------------------
// Edge kernel: for each edge e:
//   gate = g_ij[e,:] @ Wg    ([R] @ [R,128] -> [128])
//   atomicAdd(v[idx_i[e],:], gate * mj[idx_j[e],:])
// One warp per edge; lane d-range = lane*4..lane*4+3 (float4).
// ---------------------------------------------------------------------------
__global__ __launch_bounds__(256)
void edge_kernel(const float* __restrict__ g,
                 const float* __restrict__ Wg,
                 const int* __restrict__ idx_i,
                 const int* __restrict__ idx_j,
                 const float* __restrict__ mj,
                 float* __restrict__ v,
                 int E, int R) {
    __shared__ float4 Wgs[32 * 32];  // up to R=32 rows x 128 cols
    for (int i = threadIdx.x; i < R * 32; i += blockDim.x)
        Wgs[i] = reinterpret_cast<const float4*>(Wg)[i];
    __syncthreads();

    const int lane   = threadIdx.x & 31;
    const int warp   = (blockIdx.x * blockDim.x + threadIdx.x) >> 5;
    const int nwarps = (gridDim.x * blockDim.x) >> 5;

    for (int e = warp; e < E; e += nwarps) {
        float gval = (lane < R) ? g[(size_t)e * R + lane] : 0.0f;
        const int j = idx_j[e];
        const int i = idx_i[e];

        float4 acc = make_float4(0.f, 0.f, 0.f, 0.f);
        for (int r = 0; r < R; r++) {
            float gr = __shfl_sync(0xffffffffu, gval, r);
            float4 w = Wgs[r * 32 + lane];
            acc.x += gr * w.x;
            acc.y += gr * w.y;
            acc.z += gr * w.z;
            acc.w += gr * w.w;
        }

        float4 m = reinterpret_cast<const float4*>(mj)[(size_t)j * 32 + lane];
        float* vp = v + (size_t)i * D + lane * 4;
        atomicAdd(vp + 0, acc.x * m.x);
        atomicAdd(vp + 1, acc.y * m.y);
        atomicAdd(vp + 2, acc.z * m.z);
        atomicAdd(vp + 3, acc.w * m.w);
    }
}

// ---------------------------------------------------------------------------
// Host-side dispatch
// ---------------------------------------------------------------------------
static void run_mm(const float* A, const float* W, const float* b,
                   const float* base, float* out, int N,
                   bool pre, bool post) {
    dim3 grid((N + 127) / 128);
    dim3 block(256);
    if (base) {
        if (pre && post)       mm128_kernel<true,  true,  true ><<<grid, block>>>(A, W, b, base, out, N);
        else if (pre)          mm128_kernel<true,  false, true ><<<grid, block>>>(A, W, b, base, out, N);
        else if (post)         mm128_kernel<false, true,  true ><<<grid, block>>>(A, W, b, base, out, N);
        else                   mm128_kernel<false, false, true ><<<grid, block>>>(A, W, b, base, out, N);
    } else {
        if (pre && post)       mm128_kernel<true,  true,  false><<<grid, block>>>(A, W, b, nullptr, out, N);
        else if (pre)          mm128_kernel<true,  false, false><<<grid, block>>>(A, W, b, nullptr, out, N);
        else if (post)         mm128_kernel<false, true,  false><<<grid, block>>>(A, W, b, nullptr, out, N);
        else                   mm128_kernel<false, false, false><<<grid, block>>>(A, W, b, nullptr, out, N);
    }
}

extern "C" void kernel_launch(void* const* d_in, const int* in_sizes, int n_in,
                              void* d_out, int out_size) {
    const float* x     = (const float*)d_in[0];
    const float* g_ij  = (const float*)d_in[1];
    const float* Wf    = (const float*)d_in[2];
    const float* bf    = (const float*)d_in[3];
    const float* Wg    = (const float*)d_in[4];
    const float* Wj    = (const float*)d_in[5];
    const float* bj    = (const float*)d_in[6];
    const float* Wi    = (const float*)d_in[7];
    const float* bi    = (const float*)d_in[8];
    const float* u     = (const float*)d_in[9];
    const float* rWint = (const float*)d_in[10];
    const float* rbint = (const float*)d_in[11];
    const float* rWatm = (const float*)d_in[12];
    const float* rbatm = (const float*)d_in[13];
    const float* rWout = (const float*)d_in[14];
    const float* rbout = (const float*)d_in[15];
    const int*   idx_i = (const int*)d_in[16];
    const int*   idx_j = (const int*)d_in[17];

    const int N      = in_sizes[0] / D;
    const int E      = in_sizes[16];
    const int R      = in_sizes[4] / D;
    const int n_int  = in_sizes[11] / D;
    const int n_atom = in_sizes[13] / D;
    const int n_out  = in_sizes[15] / D;

    if (N > MAXN) return;

    float *xa, *xp, *mj, *v, *t1;
    cudaGetSymbolAddress((void**)&xa, d_xa);
    cudaGetSymbolAddress((void**)&xp, d_xp);
    cudaGetSymbolAddress((void**)&mj, d_mj);
    cudaGetSymbolAddress((void**)&v,  d_v);
    cudaGetSymbolAddress((void**)&t1, d_t1);

    float* o_out = (float*)d_out;                 // o -> first N*D
    float* h_out = (float*)d_out + (size_t)N * D; // h -> second N*D

    // 1) xa = ssp(x), xp = u * xa
    {
        int total = N * D;
        prolog_kernel<<<(total + 255) / 256, 256>>>(x, u, xa, xp, total);
    }

    // 2) mj = ssp(xa @ Wj + bj)   (node-level; gathered per-edge later)
    run_mm(xa, Wj, bj, nullptr, mj, N, /*pre=*/false, /*post=*/true);

    // 3) v = ssp(xa @ Wi + bi)    (the vm term; edge scatter adds on top)
    run_mm(xa, Wi, bi, nullptr, v, N, false, true);

    // 4) v += segment_sum( (g_ij @ Wg) * mj[idx_j], idx_i )
    edge_kernel<<<2048, 256>>>(g_ij, Wg, idx_i, idx_j, mj, v, E, R);

    // 5) interaction residual stack: v = residual(v, Wk, bk)
    for (int k = 0; k < n_int; k++) {
        const float* Wk = rWint + (size_t)k * D * D;
        const float* bk = rbint + (size_t)k * D;
        run_mm(v,  Wk, bk, nullptr, t1, N, true, false);   // t1 = ssp(v)@W + b
        run_mm(t1, Wk, bk, v,       v,  N, true, false);   // v  = ssp(t1)@W + b + v
    }

    // 6) h = xp + ssp(v) @ Wf + bf   -> written directly into output h region
    run_mm(v, Wf, bf, xp, h_out, N, true, false);

    // 7) atomic residual stack (in-place on h)
    for (int k = 0; k < n_atom; k++) {
        const float* Wk = rWatm + (size_t)k * D * D;
        const float* bk = rbatm + (size_t)k * D;
        run_mm(h_out, Wk, bk, nullptr, t1,    N, true, false);
        run_mm(t1,    Wk, bk, h_out,   h_out, N, true, false);
    }

    // 8) output residual stack then final ssp; o starts as h
    {
        const float* cur = h_out;
        for (int k = 0; k < n_out; k++) {
            const float* Wk = rWout + (size_t)k * D * D;
            const float* bk = rbout + (size_t)k * D;
            bool last = (k == n_out - 1);
            float* dst = last ? o_out : mj;   // mj is dead scratch by now
            run_mm(cur, Wk, bk, nullptr, t1, N, true, false);
            run_mm(t1,  Wk, bk, cur,     dst, N, true, /*post=*/last); // last: o = ssp(res)
            cur = dst;
        }
    }
}